// round 7
// baseline (speedup 1.0000x reference)
#include <cuda_runtime.h>
#include <cuda_bf16.h>
#include <cstdint>

#define N_NODES 100000
#define N_EDGES 1600000
#define N_GRAPHS 4096
#define HID 512
#define NSCAN_BLOCKS ((N_NODES + 1023) / 1024)

// ---------------- scratch (device globals; no allocation allowed) ----------------
__device__ float g_bufA[(size_t)N_NODES * HID];
__device__ float g_bufB[(size_t)N_NODES * HID];
__device__ float g_bufC[(size_t)N_NODES * HID];
__device__ float g_h7[(size_t)N_NODES * 7];
__device__ int   g_deg[N_NODES];
__device__ int   g_off[N_NODES + 1];
__device__ int   g_cur[N_NODES];
__device__ int   g_csr[N_EDGES];
__device__ int   g_bsum[NSCAN_BLOCKS];
__device__ int   g_gstart[N_GRAPHS + 1];
__device__ float g_pool[(size_t)N_GRAPHS * HID];
__device__ float g_t256[(size_t)N_GRAPHS * 256];

// ---------------- f32x2 helpers ----------------
__device__ __forceinline__ void fma2(unsigned long long& d, unsigned long long a,
                                     unsigned long long b) {
    asm("fma.rn.f32x2 %0, %1, %2, %3;" : "=l"(d) : "l"(a), "l"(b), "l"(d));
}
__device__ __forceinline__ float2 unpack2(unsigned long long v) {
    float2 r;
    asm("mov.b64 {%0, %1}, %2;" : "=f"(r.x), "=f"(r.y) : "l"(v));
    return r;
}

// ---------------- CSR build ----------------
__global__ void k_zero_deg() {
    int i = blockIdx.x * blockDim.x + threadIdx.x;
    if (i < N_NODES) g_deg[i] = 0;
}

// 4 edges per thread (N_EDGES % 4 == 0): int4 loads, 1/4 the threads
__global__ void k_hist(const int* __restrict__ dst) {
    int e4 = blockIdx.x * blockDim.x + threadIdx.x;
    if (e4 * 4 < N_EDGES) {
        int4 d = *(const int4*)&dst[e4 * 4];
        atomicAdd(&g_deg[d.x], 1);
        atomicAdd(&g_deg[d.y], 1);
        atomicAdd(&g_deg[d.z], 1);
        atomicAdd(&g_deg[d.w], 1);
    }
}

// two-level scan: (1) per-block exclusive scan + block sums
__global__ void k_scan1() {
    __shared__ int sh[1024];
    int t = threadIdx.x;
    int i = blockIdx.x * 1024 + t;
    int v = (i < N_NODES) ? g_deg[i] : 0;
    sh[t] = v;
    __syncthreads();
#pragma unroll
    for (int off = 1; off < 1024; off <<= 1) {
        int x = (t >= off) ? sh[t - off] : 0;
        __syncthreads();
        sh[t] += x;
        __syncthreads();
    }
    if (i < N_NODES) g_off[i] = sh[t] - v;  // local exclusive
    if (t == 1023) g_bsum[blockIdx.x] = sh[1023];
}

// (2) exclusive scan of the block sums (NSCAN_BLOCKS <= 128)
__global__ void k_scan2() {
    __shared__ int sh[128];
    int t = threadIdx.x;
    int v = (t < NSCAN_BLOCKS) ? g_bsum[t] : 0;
    sh[t] = v;
    __syncthreads();
#pragma unroll
    for (int off = 1; off < 128; off <<= 1) {
        int x = (t >= off) ? sh[t - off] : 0;
        __syncthreads();
        sh[t] += x;
        __syncthreads();
    }
    if (t < NSCAN_BLOCKS) g_bsum[t] = sh[t] - v;  // exclusive
}

// (3) add block offsets; also initialize g_cur and g_off[N_NODES]
__global__ void k_scan3() {
    int t = threadIdx.x;
    int i = blockIdx.x * 1024 + t;
    if (i < N_NODES) {
        int o = g_off[i] + g_bsum[blockIdx.x];
        g_off[i] = o;
        g_cur[i] = o;
    }
    if (i == 0) g_off[N_NODES] = N_EDGES;
}

// 4 edges per thread: two int4 loads, 4 scatter stores
__global__ void k_scatter(const int* __restrict__ src, const int* __restrict__ dst) {
    int e4 = blockIdx.x * blockDim.x + threadIdx.x;
    if (e4 * 4 < N_EDGES) {
        int4 s = *(const int4*)&src[e4 * 4];
        int4 d = *(const int4*)&dst[e4 * 4];
        g_csr[atomicAdd(&g_cur[d.x], 1)] = s.x;
        g_csr[atomicAdd(&g_cur[d.y], 1)] = s.y;
        g_csr[atomicAdd(&g_cur[d.z], 1)] = s.z;
        g_csr[atomicAdd(&g_cur[d.w], 1)] = s.w;
    }
}

// ---------------- graph boundaries from sorted batch ----------------
__global__ void k_gbounds(const int* __restrict__ batch) {
    int i = blockIdx.x * blockDim.x + threadIdx.x;
    if (i >= N_NODES) return;
    int b = batch[i];
    if (i == 0) {
        for (int g = 0; g <= b; ++g) g_gstart[g] = 0;
    } else {
        int bp = batch[i - 1];
        for (int g = bp + 1; g <= b; ++g) g_gstart[g] = i;
    }
    if (i == N_NODES - 1) {
        for (int g = b + 1; g <= N_GRAPHS; ++g) g_gstart[g] = N_NODES;
    }
}

// ---------------- layer-1 aggregation (7-dim) ----------------
__global__ void k_agg7(const float* __restrict__ x) {
    int v = blockIdx.x * blockDim.x + threadIdx.x;
    if (v >= N_NODES) return;
    float acc[7];
#pragma unroll
    for (int c = 0; c < 7; c++) acc[c] = x[v * 7 + c];
    int e0 = g_off[v], e1 = g_off[v + 1];
    for (int e = e0; e < e1; ++e) {
        int s = g_csr[e];
#pragma unroll
        for (int c = 0; c < 7; c++) acc[c] += x[s * 7 + c];
    }
#pragma unroll
    for (int c = 0; c < 7; c++) g_h7[v * 7 + c] = acc[c];
}

// out[v,:] = relu(h7[v,:] @ W[7,512] + b), 8 nodes per block (W held in regs,
// reused across the 8 rows -> 8x less weight traffic than 1 node/block).
#define G7_NPB 8
__global__ void k_gemm7(const float* __restrict__ W, const float* __restrict__ b,
                        float* __restrict__ out) {
    int v0 = blockIdx.x * G7_NPB;
    int t = threadIdx.x;  // 128 threads, 4 cols each
    __shared__ float xs[G7_NPB][7];
    if (t < G7_NPB * 7) {
        int n = t / 7, c = t % 7;
        int v = v0 + n;
        xs[n][c] = (v < N_NODES) ? g_h7[(size_t)v * 7 + c] : 0.f;
    }
    float4 w4[7];
#pragma unroll
    for (int k = 0; k < 7; k++) w4[k] = *(const float4*)&W[k * HID + t * 4];
    float4 bias4 = *(const float4*)&b[t * 4];
    __syncthreads();
#pragma unroll
    for (int n = 0; n < G7_NPB; ++n) {
        int v = v0 + n;
        if (v >= N_NODES) break;
        float4 acc = bias4;
#pragma unroll
        for (int k = 0; k < 7; k++) {
            float a = xs[n][k];
            acc.x += a * w4[k].x; acc.y += a * w4[k].y;
            acc.z += a * w4[k].z; acc.w += a * w4[k].w;
        }
        acc.x = fmaxf(acc.x, 0.f); acc.y = fmaxf(acc.y, 0.f);
        acc.z = fmaxf(acc.z, 0.f); acc.w = fmaxf(acc.w, 0.f);
        *(float4*)&out[(size_t)v * HID + t * 4] = acc;
    }
}

// ---------------- 512-dim aggregation: hout = hin + segment_sum(hin[src], dst) ---------
__global__ void k_agg512(const float* __restrict__ hin, float* __restrict__ hout) {
    int v = blockIdx.x;
    int t = threadIdx.x;
    int c = t * 4;
    float4 a0 = *(const float4*)&hin[(size_t)v * HID + c];
    float4 a1 = make_float4(0.f, 0.f, 0.f, 0.f);
    float4 a2 = make_float4(0.f, 0.f, 0.f, 0.f);
    float4 a3 = make_float4(0.f, 0.f, 0.f, 0.f);
    int e0 = g_off[v], e1 = g_off[v + 1];
    __shared__ int se[128];
    for (int base = e0; base < e1; base += 128) {
        int m = min(128, e1 - base);
        if (t < m) se[t] = g_csr[base + t];
        __syncthreads();
        int i = 0;
        for (; i + 4 <= m; i += 4) {
            float4 u0 = *(const float4*)&hin[(size_t)se[i + 0] * HID + c];
            float4 u1 = *(const float4*)&hin[(size_t)se[i + 1] * HID + c];
            float4 u2 = *(const float4*)&hin[(size_t)se[i + 2] * HID + c];
            float4 u3 = *(const float4*)&hin[(size_t)se[i + 3] * HID + c];
            a0.x += u0.x; a0.y += u0.y; a0.z += u0.z; a0.w += u0.w;
            a1.x += u1.x; a1.y += u1.y; a1.z += u1.z; a1.w += u1.w;
            a2.x += u2.x; a2.y += u2.y; a2.z += u2.z; a2.w += u2.w;
            a3.x += u3.x; a3.y += u3.y; a3.z += u3.z; a3.w += u3.w;
        }
        for (; i < m; ++i) {
            float4 u = *(const float4*)&hin[(size_t)se[i] * HID + c];
            a0.x += u.x; a0.y += u.y; a0.z += u.z; a0.w += u.w;
        }
        __syncthreads();
    }
    float4 acc = make_float4(a0.x + a1.x + a2.x + a3.x, a0.y + a1.y + a2.y + a3.y,
                             a0.z + a1.z + a2.z + a3.z, a0.w + a1.w + a2.w + a3.w);
    *(float4*)&hout[(size_t)v * HID + c] = acc;
}

// ---------------- SGEMM: C[M,Nn] = (relu?)(A[M,Kk] @ W[Kk,Nn] + bias) ----------------
// 128x128x16 tiles, 256 threads, 8x8 micro-tile, fma.rn.f32x2 inner loop.
// A tile stored DUPLICATED in smem (each scalar twice, adjacent) so the inner
// loop reads ready-made f32x2 operands: no per-k pack MOVs.
template <bool RELU>
__global__ __launch_bounds__(256, 2) void k_sgemm(const float* __restrict__ A,
                                                  const float* __restrict__ W,
                                                  const float* __restrict__ bias,
                                                  float* __restrict__ C, int M, int Nn,
                                                  int Kk) {
    constexpr int BM = 128, BN = 128, BK = 16;
    __shared__ float As[2][BK][2 * BM];  // duplicated pairs: As[k][2r]==As[k][2r+1]
    __shared__ float Bs[2][BK][BN];
    const int tid = threadIdx.x;
    const int bm = blockIdx.y * BM;
    const int bn = blockIdx.x * BN;
    const int tx = tid & 15, ty = tid >> 4;

    const int ar = tid >> 2;         // 0..63 (row within half-tile)
    const int ak = (tid & 3) << 2;   // 0,4,8,12
    const int bk = tid >> 5;         // 0..7
    const int bc = (tid & 31) << 2;  // 0..124

    unsigned long long acc[8][4];
#pragma unroll
    for (int i = 0; i < 8; i++)
#pragma unroll
        for (int j = 0; j < 4; j++) acc[i][j] = 0ull;

    const int nstage = Kk / BK;

    // stage 0 load
#pragma unroll
    for (int h = 0; h < 2; ++h) {
        int r = ar + h * 64;
        int row = bm + r;
        float4 a4 = make_float4(0.f, 0.f, 0.f, 0.f);
        if (row < M) a4 = *(const float4*)&A[(size_t)row * Kk + ak];
        *(float2*)&As[0][ak + 0][2 * r] = make_float2(a4.x, a4.x);
        *(float2*)&As[0][ak + 1][2 * r] = make_float2(a4.y, a4.y);
        *(float2*)&As[0][ak + 2][2 * r] = make_float2(a4.z, a4.z);
        *(float2*)&As[0][ak + 3][2 * r] = make_float2(a4.w, a4.w);
    }
#pragma unroll
    for (int h = 0; h < 2; ++h) {
        int kk = bk + h * 8;
        *(float4*)&Bs[0][kk][bc] = *(const float4*)&W[(size_t)kk * Nn + bn + bc];
    }
    __syncthreads();

    for (int s = 0; s < nstage; ++s) {
        const int cur = s & 1;
        float4 pa[2];
        float4 pb[2];
        if (s + 1 < nstage) {
            int k0 = (s + 1) * BK;
#pragma unroll
            for (int h = 0; h < 2; ++h) {
                int row = bm + ar + h * 64;
                pa[h] = make_float4(0.f, 0.f, 0.f, 0.f);
                if (row < M) pa[h] = *(const float4*)&A[(size_t)row * Kk + k0 + ak];
                pb[h] = *(const float4*)&W[(size_t)(k0 + bk + h * 8) * Nn + bn + bc];
            }
        }
#pragma unroll
        for (int k = 0; k < BK; ++k) {
            ulonglong2 A0 = *(const ulonglong2*)&As[cur][k][2 * (ty * 8) + 0];
            ulonglong2 A1 = *(const ulonglong2*)&As[cur][k][2 * (ty * 8) + 4];
            ulonglong2 A2 = *(const ulonglong2*)&As[cur][k][2 * (ty * 8) + 8];
            ulonglong2 A3 = *(const ulonglong2*)&As[cur][k][2 * (ty * 8) + 12];
            ulonglong2 bb0 = *(const ulonglong2*)&Bs[cur][k][tx * 8];
            ulonglong2 bb1 = *(const ulonglong2*)&Bs[cur][k][tx * 8 + 4];
            unsigned long long b2[4] = {bb0.x, bb0.y, bb1.x, bb1.y};
            unsigned long long a2[8] = {A0.x, A0.y, A1.x, A1.y, A2.x, A2.y, A3.x, A3.y};
#pragma unroll
            for (int i = 0; i < 8; ++i) {
#pragma unroll
                for (int j = 0; j < 4; ++j) fma2(acc[i][j], a2[i], b2[j]);
            }
        }
        if (s + 1 < nstage) {
            const int nxt = cur ^ 1;
#pragma unroll
            for (int h = 0; h < 2; ++h) {
                int r = ar + h * 64;
                *(float2*)&As[nxt][ak + 0][2 * r] = make_float2(pa[h].x, pa[h].x);
                *(float2*)&As[nxt][ak + 1][2 * r] = make_float2(pa[h].y, pa[h].y);
                *(float2*)&As[nxt][ak + 2][2 * r] = make_float2(pa[h].z, pa[h].z);
                *(float2*)&As[nxt][ak + 3][2 * r] = make_float2(pa[h].w, pa[h].w);
                *(float4*)&Bs[nxt][bk + h * 8][bc] = pb[h];
            }
            __syncthreads();
        }
    }

    float bcol[8];
#pragma unroll
    for (int j = 0; j < 8; ++j) bcol[j] = bias[bn + tx * 8 + j];
#pragma unroll
    for (int i = 0; i < 8; ++i) {
        int row = bm + ty * 8 + i;
        if (row < M) {
            float2 p0 = unpack2(acc[i][0]);
            float2 p1 = unpack2(acc[i][1]);
            float2 p2 = unpack2(acc[i][2]);
            float2 p3 = unpack2(acc[i][3]);
            float4 o0 = make_float4(p0.x + bcol[0], p0.y + bcol[1], p1.x + bcol[2],
                                    p1.y + bcol[3]);
            float4 o1 = make_float4(p2.x + bcol[4], p2.y + bcol[5], p3.x + bcol[6],
                                    p3.y + bcol[7]);
            if (RELU) {
                o0.x = fmaxf(o0.x, 0.f); o0.y = fmaxf(o0.y, 0.f);
                o0.z = fmaxf(o0.z, 0.f); o0.w = fmaxf(o0.w, 0.f);
                o1.x = fmaxf(o1.x, 0.f); o1.y = fmaxf(o1.y, 0.f);
                o1.z = fmaxf(o1.z, 0.f); o1.w = fmaxf(o1.w, 0.f);
            }
            *(float4*)&C[(size_t)row * Nn + bn + tx * 8] = o0;
            *(float4*)&C[(size_t)row * Nn + bn + tx * 8 + 4] = o1;
        }
    }
}

// ---------------- mean pool over contiguous node ranges (batch sorted) ----------------
__global__ void k_pool2(const float* __restrict__ h) {
    int g = blockIdx.x;
    int t = threadIdx.x;
    int c = t * 4;
    int r0 = g_gstart[g], r1 = g_gstart[g + 1];
    float4 a0 = make_float4(0.f, 0.f, 0.f, 0.f);
    float4 a1 = make_float4(0.f, 0.f, 0.f, 0.f);
    int v = r0;
    for (; v + 2 <= r1; v += 2) {
        float4 u0 = *(const float4*)&h[(size_t)(v + 0) * HID + c];
        float4 u1 = *(const float4*)&h[(size_t)(v + 1) * HID + c];
        a0.x += u0.x; a0.y += u0.y; a0.z += u0.z; a0.w += u0.w;
        a1.x += u1.x; a1.y += u1.y; a1.z += u1.z; a1.w += u1.w;
    }
    if (v < r1) {
        float4 u = *(const float4*)&h[(size_t)v * HID + c];
        a0.x += u.x; a0.y += u.y; a0.z += u.z; a0.w += u.w;
    }
    float inv = 1.0f / fmaxf((float)(r1 - r0), 1.0f);
    float4 acc = make_float4((a0.x + a1.x) * inv, (a0.y + a1.y) * inv,
                             (a0.z + a1.z) * inv, (a0.w + a1.w) * inv);
    *(float4*)&g_pool[(size_t)g * HID + c] = acc;
}

// ---------------- head: out[g,12] = t256[g,:] @ W[256,12] + b ----------------
__global__ void k_head2(const float* __restrict__ W, const float* __restrict__ b,
                        float* __restrict__ out) {
    int g = blockIdx.x;
    int t = threadIdx.x;  // 128
    __shared__ float s[256];
    s[t] = g_t256[(size_t)g * 256 + t];
    s[t + 128] = g_t256[(size_t)g * 256 + t + 128];
    __syncthreads();
    if (t < 12) {
        float acc = b[t];
        for (int k = 0; k < 256; ++k) acc += s[k] * W[k * 12 + t];
        out[g * 12 + t] = acc;
    }
}

// ---------------- launch ----------------
extern "C" void kernel_launch(void* const* d_in, const int* in_sizes, int n_in,
                              void* d_out, int out_size) {
    const float* x = (const float*)d_in[0];
    const int* ei = (const int*)d_in[1];
    const int* batch = (const int*)d_in[2];
    const float* c1_w1 = (const float*)d_in[3];
    const float* c1_b1 = (const float*)d_in[4];
    const float* c1_w2 = (const float*)d_in[5];
    const float* c1_b2 = (const float*)d_in[6];
    const float* c2_w1 = (const float*)d_in[7];
    const float* c2_b1 = (const float*)d_in[8];
    const float* c2_w2 = (const float*)d_in[9];
    const float* c2_b2 = (const float*)d_in[10];
    const float* c3_w1 = (const float*)d_in[11];
    const float* c3_b1 = (const float*)d_in[12];
    const float* c3_w2 = (const float*)d_in[13];
    const float* c3_b2 = (const float*)d_in[14];
    const float* lin_w1 = (const float*)d_in[15];
    const float* lin_b1 = (const float*)d_in[16];
    const float* lin_w2 = (const float*)d_in[17];
    const float* lin_b2 = (const float*)d_in[18];
    float* out = (float*)d_out;

    const int* src = ei;
    const int* dst = ei + N_EDGES;

    float *bufA, *bufB, *bufC, *pool, *t256;
    cudaGetSymbolAddress((void**)&bufA, g_bufA);
    cudaGetSymbolAddress((void**)&bufB, g_bufB);
    cudaGetSymbolAddress((void**)&bufC, g_bufC);
    cudaGetSymbolAddress((void**)&pool, g_pool);
    cudaGetSymbolAddress((void**)&t256, g_t256);

    // CSR build (by dst) + graph boundaries
    k_zero_deg<<<(N_NODES + 255) / 256, 256>>>();
    k_hist<<<(N_EDGES / 4 + 255) / 256, 256>>>(dst);
    k_scan1<<<NSCAN_BLOCKS, 1024>>>();
    k_scan2<<<1, 128>>>();
    k_scan3<<<NSCAN_BLOCKS, 1024>>>();
    k_scatter<<<(N_EDGES / 4 + 255) / 256, 256>>>(src, dst);
    k_gbounds<<<(N_NODES + 255) / 256, 256>>>(batch);

    dim3 gconv(HID / 128, (N_NODES + 127) / 128);

    // conv1
    k_agg7<<<(N_NODES + 127) / 128, 128>>>(x);
    k_gemm7<<<(N_NODES + G7_NPB - 1) / G7_NPB, 128>>>(c1_w1, c1_b1, bufA);
    k_sgemm<true><<<gconv, 256>>>(bufA, c1_w2, c1_b2, bufB, N_NODES, HID, HID);

    // conv2
    k_agg512<<<N_NODES, 128>>>(bufB, bufC);
    k_sgemm<true><<<gconv, 256>>>(bufC, c2_w1, c2_b1, bufA, N_NODES, HID, HID);
    k_sgemm<true><<<gconv, 256>>>(bufA, c2_w2, c2_b2, bufB, N_NODES, HID, HID);

    // conv3
    k_agg512<<<N_NODES, 128>>>(bufB, bufC);
    k_sgemm<true><<<gconv, 256>>>(bufC, c3_w1, c3_b1, bufA, N_NODES, HID, HID);
    k_sgemm<true><<<gconv, 256>>>(bufA, c3_w2, c3_b2, bufB, N_NODES, HID, HID);

    // mean pool (no atomics; batch is sorted)
    k_pool2<<<N_GRAPHS, 128>>>(bufB);

    // head
    dim3 ghead(256 / 128, (N_GRAPHS + 127) / 128);
    k_sgemm<true><<<ghead, 256>>>(pool, lin_w1, lin_b1, t256, N_GRAPHS, 256, HID);
    k_head2<<<N_GRAPHS, 128>>>(lin_w2, lin_b2, out);
}

// round 17
// speedup vs baseline: 2.6069x; 2.6069x over previous
#include <cuda_runtime.h>
#include <cuda_bf16.h>
#include <cstdint>

#define N_NODES 100000
#define N_EDGES 1600000
#define N_GRAPHS 4096
#define HID 512
#define NSCAN_BLOCKS ((N_NODES + 1023) / 1024)

// ---------------- scratch (device globals; no allocation allowed) ----------------
__device__ float g_h7[(size_t)N_NODES * 7];
__device__ __nv_bfloat16 g_hiA[(size_t)N_NODES * HID];
__device__ __nv_bfloat16 g_loA[(size_t)N_NODES * HID];
__device__ __nv_bfloat16 g_hiB[(size_t)N_NODES * HID];
__device__ __nv_bfloat16 g_loB[(size_t)N_NODES * HID];
__device__ __nv_bfloat16 g_hiC[(size_t)N_NODES * HID];
__device__ __nv_bfloat16 g_loC[(size_t)N_NODES * HID];
__device__ __nv_bfloat16 g_wth[5][HID * HID];  // transposed weights [n][k], hi part
__device__ __nv_bfloat16 g_wtl[5][HID * HID];  // transposed weights [n][k], lo part
__device__ int   g_deg[N_NODES];
__device__ int   g_off[N_NODES + 1];
__device__ int   g_cur[N_NODES];
__device__ int   g_csr[N_EDGES];
__device__ int   g_bsum[NSCAN_BLOCKS];
__device__ int   g_gstart[N_GRAPHS + 1];
__device__ float g_pool[(size_t)N_GRAPHS * HID];
__device__ float g_t256[(size_t)N_GRAPHS * 256];

// ---------------- small helpers ----------------
__device__ __forceinline__ void fma2(unsigned long long& d, unsigned long long a,
                                     unsigned long long b) {
    asm("fma.rn.f32x2 %0, %1, %2, %3;" : "=l"(d) : "l"(a), "l"(b), "l"(d));
}
__device__ __forceinline__ float2 unpack2(unsigned long long v) {
    float2 r;
    asm("mov.b64 {%0, %1}, %2;" : "=f"(r.x), "=f"(r.y) : "l"(v));
    return r;
}
__device__ __forceinline__ uint32_t smem_u32(const void* p) {
    uint32_t a;
    asm("{ .reg .u64 t; cvta.to.shared.u64 t, %1; cvt.u32.u64 %0, t; }" : "=r"(a) : "l"(p));
    return a;
}
#define SWZ128(o) ((o) ^ (((o) >> 3) & 0x70))

// base-ISA tensor ops (no sm_103a-only features)
__device__ __forceinline__ void ldsm4(uint32_t* r, uint32_t addr) {
    asm volatile("ldmatrix.sync.aligned.m8n8.x4.shared.b16 {%0,%1,%2,%3}, [%4];"
                 : "=r"(r[0]), "=r"(r[1]), "=r"(r[2]), "=r"(r[3]) : "r"(addr));
}
__device__ __forceinline__ void mma16816(float* d, const uint32_t* a, uint32_t b0,
                                         uint32_t b1) {
    asm volatile(
        "mma.sync.aligned.m16n8k16.row.col.f32.bf16.bf16.f32 "
        "{%0,%1,%2,%3}, {%4,%5,%6,%7}, {%8,%9}, {%0,%1,%2,%3};"
        : "+f"(d[0]), "+f"(d[1]), "+f"(d[2]), "+f"(d[3])
        : "r"(a[0]), "r"(a[1]), "r"(a[2]), "r"(a[3]), "r"(b0), "r"(b1));
}

// split/pair helpers
__device__ __forceinline__ void split_store4(float4 v, __nv_bfloat16* hp, __nv_bfloat16* lp) {
    __nv_bfloat16 h[4], l[4];
    float vv[4] = {v.x, v.y, v.z, v.w};
#pragma unroll
    for (int i = 0; i < 4; i++) {
        h[i] = __float2bfloat16(vv[i]);
        l[i] = __float2bfloat16(vv[i] - __bfloat162float(h[i]));
    }
    *(uint2*)hp = *(uint2*)h;
    *(uint2*)lp = *(uint2*)l;
}
__device__ __forceinline__ void split_store2(float x, float y, __nv_bfloat16* hp,
                                             __nv_bfloat16* lp) {
    __nv_bfloat16 h[2], l[2];
    h[0] = __float2bfloat16(x);
    l[0] = __float2bfloat16(x - __bfloat162float(h[0]));
    h[1] = __float2bfloat16(y);
    l[1] = __float2bfloat16(y - __bfloat162float(h[1]));
    *(uint32_t*)hp = *(uint32_t*)h;
    *(uint32_t*)lp = *(uint32_t*)l;
}
__device__ __forceinline__ float4 load_pair4(const __nv_bfloat16* hp, const __nv_bfloat16* lp) {
    uint2 hu = *(const uint2*)hp, lu = *(const uint2*)lp;
    const __nv_bfloat16* hb = (const __nv_bfloat16*)&hu;
    const __nv_bfloat16* lb = (const __nv_bfloat16*)&lu;
    float4 r;
    r.x = __bfloat162float(hb[0]) + __bfloat162float(lb[0]);
    r.y = __bfloat162float(hb[1]) + __bfloat162float(lb[1]);
    r.z = __bfloat162float(hb[2]) + __bfloat162float(lb[2]);
    r.w = __bfloat162float(hb[3]) + __bfloat162float(lb[3]);
    return r;
}

// ---------------- CSR build ----------------
__global__ void k_zero_deg() {
    int i = blockIdx.x * blockDim.x + threadIdx.x;
    if (i < N_NODES) g_deg[i] = 0;
}
__global__ void k_hist(const int* __restrict__ dst) {
    int e4 = blockIdx.x * blockDim.x + threadIdx.x;
    if (e4 * 4 < N_EDGES) {
        int4 d = *(const int4*)&dst[e4 * 4];
        atomicAdd(&g_deg[d.x], 1);
        atomicAdd(&g_deg[d.y], 1);
        atomicAdd(&g_deg[d.z], 1);
        atomicAdd(&g_deg[d.w], 1);
    }
}
__global__ void k_scan1() {
    __shared__ int sh[1024];
    int t = threadIdx.x;
    int i = blockIdx.x * 1024 + t;
    int v = (i < N_NODES) ? g_deg[i] : 0;
    sh[t] = v;
    __syncthreads();
#pragma unroll
    for (int off = 1; off < 1024; off <<= 1) {
        int x = (t >= off) ? sh[t - off] : 0;
        __syncthreads();
        sh[t] += x;
        __syncthreads();
    }
    if (i < N_NODES) g_off[i] = sh[t] - v;
    if (t == 1023) g_bsum[blockIdx.x] = sh[1023];
}
__global__ void k_scan2() {
    __shared__ int sh[128];
    int t = threadIdx.x;
    int v = (t < NSCAN_BLOCKS) ? g_bsum[t] : 0;
    sh[t] = v;
    __syncthreads();
#pragma unroll
    for (int off = 1; off < 128; off <<= 1) {
        int x = (t >= off) ? sh[t - off] : 0;
        __syncthreads();
        sh[t] += x;
        __syncthreads();
    }
    if (t < NSCAN_BLOCKS) g_bsum[t] = sh[t] - v;
}
__global__ void k_scan3() {
    int t = threadIdx.x;
    int i = blockIdx.x * 1024 + t;
    if (i < N_NODES) {
        int o = g_off[i] + g_bsum[blockIdx.x];
        g_off[i] = o;
        g_cur[i] = o;
    }
    if (i == 0) g_off[N_NODES] = N_EDGES;
}
__global__ void k_scatter(const int* __restrict__ src, const int* __restrict__ dst) {
    int e4 = blockIdx.x * blockDim.x + threadIdx.x;
    if (e4 * 4 < N_EDGES) {
        int4 s = *(const int4*)&src[e4 * 4];
        int4 d = *(const int4*)&dst[e4 * 4];
        g_csr[atomicAdd(&g_cur[d.x], 1)] = s.x;
        g_csr[atomicAdd(&g_cur[d.y], 1)] = s.y;
        g_csr[atomicAdd(&g_cur[d.z], 1)] = s.z;
        g_csr[atomicAdd(&g_cur[d.w], 1)] = s.w;
    }
}
__global__ void k_gbounds(const int* __restrict__ batch) {
    int i = blockIdx.x * blockDim.x + threadIdx.x;
    if (i >= N_NODES) return;
    int b = batch[i];
    if (i == 0) {
        for (int g = 0; g <= b; ++g) g_gstart[g] = 0;
    } else {
        int bp = batch[i - 1];
        for (int g = bp + 1; g <= b; ++g) g_gstart[g] = i;
    }
    if (i == N_NODES - 1) {
        for (int g = b + 1; g <= N_GRAPHS; ++g) g_gstart[g] = N_NODES;
    }
}

// ---------------- weight transpose + split:  wt[n*512+k] = split(W[k*512+n]) ----------------
__global__ void k_wprep(const float* __restrict__ W, __nv_bfloat16* __restrict__ th,
                        __nv_bfloat16* __restrict__ tl) {
    int idx = blockIdx.x * blockDim.x + threadIdx.x;  // n*512 + k
    if (idx >= HID * HID) return;
    int n = idx >> 9, k = idx & 511;
    float v = W[k * HID + n];
    __nv_bfloat16 h = __float2bfloat16(v);
    th[idx] = h;
    tl[idx] = __float2bfloat16(v - __bfloat162float(h));
}

// ---------------- layer-1 aggregation (7-dim) ----------------
__global__ void k_agg7(const float* __restrict__ x) {
    int v = blockIdx.x * blockDim.x + threadIdx.x;
    if (v >= N_NODES) return;
    float acc[7];
#pragma unroll
    for (int c = 0; c < 7; c++) acc[c] = x[v * 7 + c];
    int e0 = g_off[v], e1 = g_off[v + 1];
    for (int e = e0; e < e1; ++e) {
        int s = g_csr[e];
#pragma unroll
        for (int c = 0; c < 7; c++) acc[c] += x[s * 7 + c];
    }
#pragma unroll
    for (int c = 0; c < 7; c++) g_h7[v * 7 + c] = acc[c];
}

// out = relu(h7 @ W[7,512] + b) -> split hi/lo, 8 nodes per block
#define G7_NPB 8
__global__ void k_gemm7(const float* __restrict__ W, const float* __restrict__ b,
                        __nv_bfloat16* __restrict__ oh, __nv_bfloat16* __restrict__ ol) {
    int v0 = blockIdx.x * G7_NPB;
    int t = threadIdx.x;
    __shared__ float xs[G7_NPB][7];
    if (t < G7_NPB * 7) {
        int n = t / 7, c = t % 7;
        int v = v0 + n;
        xs[n][c] = (v < N_NODES) ? g_h7[(size_t)v * 7 + c] : 0.f;
    }
    float4 w4[7];
#pragma unroll
    for (int k = 0; k < 7; k++) w4[k] = *(const float4*)&W[k * HID + t * 4];
    float4 bias4 = *(const float4*)&b[t * 4];
    __syncthreads();
#pragma unroll
    for (int n = 0; n < G7_NPB; ++n) {
        int v = v0 + n;
        if (v >= N_NODES) break;
        float4 acc = bias4;
#pragma unroll
        for (int k = 0; k < 7; k++) {
            float a = xs[n][k];
            acc.x += a * w4[k].x; acc.y += a * w4[k].y;
            acc.z += a * w4[k].z; acc.w += a * w4[k].w;
        }
        acc.x = fmaxf(acc.x, 0.f); acc.y = fmaxf(acc.y, 0.f);
        acc.z = fmaxf(acc.z, 0.f); acc.w = fmaxf(acc.w, 0.f);
        split_store4(acc, &oh[(size_t)v * HID + t * 4], &ol[(size_t)v * HID + t * 4]);
    }
}

// ---------------- 512-dim aggregation on (hi,lo) pairs ----------------
__global__ void k_agg512(const __nv_bfloat16* __restrict__ ih, const __nv_bfloat16* __restrict__ il,
                         __nv_bfloat16* __restrict__ oh, __nv_bfloat16* __restrict__ ol) {
    int v = blockIdx.x;
    int t = threadIdx.x;
    int c = t * 4;
    float4 a0 = load_pair4(&ih[(size_t)v * HID + c], &il[(size_t)v * HID + c]);
    float4 a1 = make_float4(0.f, 0.f, 0.f, 0.f);
    int e0 = g_off[v], e1 = g_off[v + 1];
    __shared__ int se[128];
    for (int base = e0; base < e1; base += 128) {
        int m = min(128, e1 - base);
        if (t < m) se[t] = g_csr[base + t];
        __syncthreads();
        int i = 0;
        for (; i + 2 <= m; i += 2) {
            float4 u0 = load_pair4(&ih[(size_t)se[i + 0] * HID + c], &il[(size_t)se[i + 0] * HID + c]);
            float4 u1 = load_pair4(&ih[(size_t)se[i + 1] * HID + c], &il[(size_t)se[i + 1] * HID + c]);
            a0.x += u0.x; a0.y += u0.y; a0.z += u0.z; a0.w += u0.w;
            a1.x += u1.x; a1.y += u1.y; a1.z += u1.z; a1.w += u1.w;
        }
        if (i < m) {
            float4 u = load_pair4(&ih[(size_t)se[i] * HID + c], &il[(size_t)se[i] * HID + c]);
            a0.x += u.x; a0.y += u.y; a0.z += u.z; a0.w += u.w;
        }
        __syncthreads();
    }
    float4 acc = make_float4(a0.x + a1.x, a0.y + a1.y, a0.z + a1.z, a0.w + a1.w);
    split_store4(acc, &oh[(size_t)v * HID + c], &ol[(size_t)v * HID + c]);
}

// ---------------- mma.sync split-bf16 GEMM ----------------
// C[M,512] = relu(A[M,512] @ W[512,512] + bias); A = Ahi+Alo, W^T (n-major,k-contig)
// = Bhi+Blo. Computes Ahi*Bhi + Ahi*Blo + Alo*Bhi with fp32 accumulators.
// CTA tile 128x128, 8 warps each 64x32, k-chunk 64, SW128-swizzled smem + ldmatrix.
// A fragments loaded inside the ma loop to cap live registers (~105 < 128).
#define OFF_BIAS 0
#define OFF_AH 1024
#define OFF_AL (OFF_AH + 16384)
#define OFF_BH (OFF_AL + 16384)
#define OFF_BL (OFF_BH + 16384)
#define TG_SMEM (OFF_BL + 16384)

__global__ __launch_bounds__(256, 2) void k_tgemm(
    const __nv_bfloat16* __restrict__ ah, const __nv_bfloat16* __restrict__ al,
    const __nv_bfloat16* __restrict__ bh, const __nv_bfloat16* __restrict__ bl,
    const float* __restrict__ bias,
    __nv_bfloat16* __restrict__ oh, __nv_bfloat16* __restrict__ ol, int M) {
    extern __shared__ __align__(1024) char sm[];
    uint32_t sbase = smem_u32(sm);
    const int tid = threadIdx.x;
    const int wid = tid >> 5;
    const int lane = tid & 31;
    const int bm = blockIdx.y * 128;
    const int bn = blockIdx.x * 128;
    const int wm = (wid & 1) * 64;   // warp m-offset in tile
    const int wn = (wid >> 1) * 32;  // warp n-offset in tile

    if (tid < 128) ((float*)(sm + OFF_BIAS))[tid] = bias[bn + tid];

    float acc[4][4][4];
#pragma unroll
    for (int i = 0; i < 4; i++)
#pragma unroll
        for (int j = 0; j < 4; j++)
#pragma unroll
            for (int q = 0; q < 4; q++) acc[i][j][q] = 0.f;

    // ldmatrix lane->row/byte mappings (within warp)
    const int a_row = wm + (lane & 7) + ((lane >> 3) & 1) * 8;  // + ma*16
    const int a_kb0 = (lane >> 4) * 16;                          // + s*32
    const int b_nrow = (lane >> 4) * 8 + (lane & 7);             // + wn + p*16
    const int b_kb0 = ((lane >> 3) & 1) * 16;                    // + s*32

    for (int ch = 0; ch < 8; ++ch) {
        int k0 = ch * 64;
        __syncthreads();  // previous chunk's compute done before overwrite
        // load 4 tiles (each 128 rows x 128B), 16B units, coalesced
#pragma unroll
        for (int i = 0; i < 16; ++i) {
            int u = tid + i * 256;   // 0..4095
            int tile = u >> 10;      // 0:Ah 1:Al 2:Bh 3:Bl
            int w = u & 1023;
            int row = w >> 3;
            int j = w & 7;           // 16B unit in row
            char* dstp = sm + OFF_AH + tile * 16384 + SWZ128(row * 128 + j * 16);
            if (tile < 2) {
                int gr = bm + row;
                if (gr < M) {
                    const __nv_bfloat16* gp = (tile == 0 ? ah : al) + (size_t)gr * HID + k0 + j * 8;
                    *(uint4*)dstp = *(const uint4*)gp;
                }
            } else {
                const __nv_bfloat16* gp = (tile == 2 ? bh : bl) + (size_t)(bn + row) * HID + k0 + j * 8;
                *(uint4*)dstp = *(const uint4*)gp;
            }
        }
        __syncthreads();

#pragma unroll
        for (int s = 0; s < 4; ++s) {
            uint32_t fbh[2][4], fbl[2][4];
            int akb = s * 32 + a_kb0;
            int bkb = s * 32 + b_kb0;
#pragma unroll
            for (int p = 0; p < 2; ++p) {
                uint32_t off = SWZ128((uint32_t)((wn + p * 16 + b_nrow) * 128 + bkb));
                ldsm4(fbh[p], sbase + OFF_BH + off);
                ldsm4(fbl[p], sbase + OFF_BL + off);
            }
#pragma unroll
            for (int ma = 0; ma < 4; ++ma) {
                uint32_t fah[4], fal[4];
                uint32_t off = SWZ128((uint32_t)((a_row + ma * 16) * 128 + akb));
                ldsm4(fah, sbase + OFF_AH + off);
                ldsm4(fal, sbase + OFF_AL + off);
#pragma unroll
                for (int na = 0; na < 4; ++na) {
                    uint32_t bh0 = fbh[na >> 1][(na & 1) * 2];
                    uint32_t bh1 = fbh[na >> 1][(na & 1) * 2 + 1];
                    uint32_t bl0 = fbl[na >> 1][(na & 1) * 2];
                    uint32_t bl1 = fbl[na >> 1][(na & 1) * 2 + 1];
                    mma16816(acc[ma][na], fah, bh0, bh1);
                    mma16816(acc[ma][na], fah, bl0, bl1);
                    mma16816(acc[ma][na], fal, bh0, bh1);
                }
            }
        }
    }

    // epilogue: bias + relu + split-store
    const float* bias_sm = (const float*)(sm + OFF_BIAS);
#pragma unroll
    for (int ma = 0; ma < 4; ++ma) {
        int r0 = bm + wm + ma * 16 + (lane >> 2);
#pragma unroll
        for (int na = 0; na < 4; ++na) {
            int col = wn + na * 8 + (lane & 3) * 2;
            float b0 = bias_sm[col], b1 = bias_sm[col + 1];
            float v0 = fmaxf(acc[ma][na][0] + b0, 0.f);
            float v1 = fmaxf(acc[ma][na][1] + b1, 0.f);
            float v2 = fmaxf(acc[ma][na][2] + b0, 0.f);
            float v3 = fmaxf(acc[ma][na][3] + b1, 0.f);
            if (r0 < M) {
                size_t o = (size_t)r0 * HID + bn + col;
                split_store2(v0, v1, &oh[o], &ol[o]);
            }
            if (r0 + 8 < M) {
                size_t o = (size_t)(r0 + 8) * HID + bn + col;
                split_store2(v2, v3, &oh[o], &ol[o]);
            }
        }
    }
}

// ---------------- mean pool over contiguous node ranges (reads hi/lo pairs) ----------------
__global__ void k_pool2(const __nv_bfloat16* __restrict__ ih, const __nv_bfloat16* __restrict__ il) {
    int g = blockIdx.x;
    int t = threadIdx.x;
    int c = t * 4;
    int r0 = g_gstart[g], r1 = g_gstart[g + 1];
    float4 a0 = make_float4(0.f, 0.f, 0.f, 0.f);
    for (int v = r0; v < r1; ++v) {
        float4 u = load_pair4(&ih[(size_t)v * HID + c], &il[(size_t)v * HID + c]);
        a0.x += u.x; a0.y += u.y; a0.z += u.z; a0.w += u.w;
    }
    float inv = 1.0f / fmaxf((float)(r1 - r0), 1.0f);
    float4 acc = make_float4(a0.x * inv, a0.y * inv, a0.z * inv, a0.w * inv);
    *(float4*)&g_pool[(size_t)g * HID + c] = acc;
}

// ---------------- fp32 FFMA2 SGEMM (head only) ----------------
template <bool RELU>
__global__ __launch_bounds__(256, 2) void k_sgemm(const float* __restrict__ A,
                                                  const float* __restrict__ W,
                                                  const float* __restrict__ bias,
                                                  float* __restrict__ C, int M, int Nn,
                                                  int Kk) {
    constexpr int BM = 128, BN = 128, BK = 16;
    __shared__ float As[2][BK][2 * BM];
    __shared__ float Bs[2][BK][BN];
    const int tid = threadIdx.x;
    const int bm = blockIdx.y * BM;
    const int bn = blockIdx.x * BN;
    const int tx = tid & 15, ty = tid >> 4;
    const int ar = tid >> 2;
    const int ak = (tid & 3) << 2;
    const int bk = tid >> 5;
    const int bc = (tid & 31) << 2;

    unsigned long long acc[8][4];
#pragma unroll
    for (int i = 0; i < 8; i++)
#pragma unroll
        for (int j = 0; j < 4; j++) acc[i][j] = 0ull;

    const int nstage = Kk / BK;
#pragma unroll
    for (int h = 0; h < 2; ++h) {
        int r = ar + h * 64;
        int row = bm + r;
        float4 a4 = make_float4(0.f, 0.f, 0.f, 0.f);
        if (row < M) a4 = *(const float4*)&A[(size_t)row * Kk + ak];
        *(float2*)&As[0][ak + 0][2 * r] = make_float2(a4.x, a4.x);
        *(float2*)&As[0][ak + 1][2 * r] = make_float2(a4.y, a4.y);
        *(float2*)&As[0][ak + 2][2 * r] = make_float2(a4.z, a4.z);
        *(float2*)&As[0][ak + 3][2 * r] = make_float2(a4.w, a4.w);
    }
#pragma unroll
    for (int h = 0; h < 2; ++h) {
        int kk = bk + h * 8;
        *(float4*)&Bs[0][kk][bc] = *(const float4*)&W[(size_t)kk * Nn + bn + bc];
    }
    __syncthreads();

    for (int s = 0; s < nstage; ++s) {
        const int cur = s & 1;
        float4 pa[2], pb[2];
        if (s + 1 < nstage) {
            int k0 = (s + 1) * BK;
#pragma unroll
            for (int h = 0; h < 2; ++h) {
                int row = bm + ar + h * 64;
                pa[h] = make_float4(0.f, 0.f, 0.f, 0.f);
                if (row < M) pa[h] = *(const float4*)&A[(size_t)row * Kk + k0 + ak];
                pb[h] = *(const float4*)&W[(size_t)(k0 + bk + h * 8) * Nn + bn + bc];
            }
        }
#pragma unroll
        for (int k = 0; k < BK; ++k) {
            ulonglong2 A0 = *(const ulonglong2*)&As[cur][k][2 * (ty * 8) + 0];
            ulonglong2 A1 = *(const ulonglong2*)&As[cur][k][2 * (ty * 8) + 4];
            ulonglong2 A2 = *(const ulonglong2*)&As[cur][k][2 * (ty * 8) + 8];
            ulonglong2 A3 = *(const ulonglong2*)&As[cur][k][2 * (ty * 8) + 12];
            ulonglong2 bb0 = *(const ulonglong2*)&Bs[cur][k][tx * 8];
            ulonglong2 bb1 = *(const ulonglong2*)&Bs[cur][k][tx * 8 + 4];
            unsigned long long b2[4] = {bb0.x, bb0.y, bb1.x, bb1.y};
            unsigned long long a2[8] = {A0.x, A0.y, A1.x, A1.y, A2.x, A2.y, A3.x, A3.y};
#pragma unroll
            for (int i = 0; i < 8; ++i)
#pragma unroll
                for (int j = 0; j < 4; ++j) fma2(acc[i][j], a2[i], b2[j]);
        }
        if (s + 1 < nstage) {
            const int nxt = cur ^ 1;
#pragma unroll
            for (int h = 0; h < 2; ++h) {
                int r = ar + h * 64;
                *(float2*)&As[nxt][ak + 0][2 * r] = make_float2(pa[h].x, pa[h].x);
                *(float2*)&As[nxt][ak + 1][2 * r] = make_float2(pa[h].y, pa[h].y);
                *(float2*)&As[nxt][ak + 2][2 * r] = make_float2(pa[h].z, pa[h].z);
                *(float2*)&As[nxt][ak + 3][2 * r] = make_float2(pa[h].w, pa[h].w);
                *(float4*)&Bs[nxt][bk + h * 8][bc] = pb[h];
            }
            __syncthreads();
        }
    }

    float bcol[8];
#pragma unroll
    for (int j = 0; j < 8; ++j) bcol[j] = bias[bn + tx * 8 + j];
#pragma unroll
    for (int i = 0; i < 8; ++i) {
        int row = bm + ty * 8 + i;
        if (row < M) {
            float2 p0 = unpack2(acc[i][0]);
            float2 p1 = unpack2(acc[i][1]);
            float2 p2 = unpack2(acc[i][2]);
            float2 p3 = unpack2(acc[i][3]);
            float4 o0 = make_float4(p0.x + bcol[0], p0.y + bcol[1], p1.x + bcol[2], p1.y + bcol[3]);
            float4 o1 = make_float4(p2.x + bcol[4], p2.y + bcol[5], p3.x + bcol[6], p3.y + bcol[7]);
            if (RELU) {
                o0.x = fmaxf(o0.x, 0.f); o0.y = fmaxf(o0.y, 0.f);
                o0.z = fmaxf(o0.z, 0.f); o0.w = fmaxf(o0.w, 0.f);
                o1.x = fmaxf(o1.x, 0.f); o1.y = fmaxf(o1.y, 0.f);
                o1.z = fmaxf(o1.z, 0.f); o1.w = fmaxf(o1.w, 0.f);
            }
            *(float4*)&C[(size_t)row * Nn + bn + tx * 8] = o0;
            *(float4*)&C[(size_t)row * Nn + bn + tx * 8 + 4] = o1;
        }
    }
}

// ---------------- head: out[g,12] = t256[g,:] @ W[256,12] + b ----------------
__global__ void k_head2(const float* __restrict__ W, const float* __restrict__ b,
                        float* __restrict__ out) {
    int g = blockIdx.x;
    int t = threadIdx.x;
    __shared__ float s[256];
    s[t] = g_t256[(size_t)g * 256 + t];
    s[t + 128] = g_t256[(size_t)g * 256 + t + 128];
    __syncthreads();
    if (t < 12) {
        float acc = b[t];
        for (int k = 0; k < 256; ++k) acc += s[k] * W[k * 12 + t];
        out[g * 12 + t] = acc;
    }
}

// ---------------- launch ----------------
extern "C" void kernel_launch(void* const* d_in, const int* in_sizes, int n_in,
                              void* d_out, int out_size) {
    const float* x = (const float*)d_in[0];
    const int* ei = (const int*)d_in[1];
    const int* batch = (const int*)d_in[2];
    const float* c1_w1 = (const float*)d_in[3];
    const float* c1_b1 = (const float*)d_in[4];
    const float* c1_w2 = (const float*)d_in[5];
    const float* c1_b2 = (const float*)d_in[6];
    const float* c2_w1 = (const float*)d_in[7];
    const float* c2_b1 = (const float*)d_in[8];
    const float* c2_w2 = (const float*)d_in[9];
    const float* c2_b2 = (const float*)d_in[10];
    const float* c3_w1 = (const float*)d_in[11];
    const float* c3_b1 = (const float*)d_in[12];
    const float* c3_w2 = (const float*)d_in[13];
    const float* c3_b2 = (const float*)d_in[14];
    const float* lin_w1 = (const float*)d_in[15];
    const float* lin_b1 = (const float*)d_in[16];
    const float* lin_w2 = (const float*)d_in[17];
    const float* lin_b2 = (const float*)d_in[18];
    float* out = (float*)d_out;

    const int* src = ei;
    const int* dst = ei + N_EDGES;

    __nv_bfloat16 *hiA, *loA, *hiB, *loB, *hiC, *loC, *wth, *wtl;
    float *pool, *t256;
    cudaGetSymbolAddress((void**)&hiA, g_hiA);
    cudaGetSymbolAddress((void**)&loA, g_loA);
    cudaGetSymbolAddress((void**)&hiB, g_hiB);
    cudaGetSymbolAddress((void**)&loB, g_loB);
    cudaGetSymbolAddress((void**)&hiC, g_hiC);
    cudaGetSymbolAddress((void**)&loC, g_loC);
    cudaGetSymbolAddress((void**)&wth, g_wth);
    cudaGetSymbolAddress((void**)&wtl, g_wtl);
    cudaGetSymbolAddress((void**)&pool, g_pool);
    cudaGetSymbolAddress((void**)&t256, g_t256);

    cudaFuncSetAttribute(k_tgemm, cudaFuncAttributeMaxDynamicSharedMemorySize, TG_SMEM);

    // CSR build + graph boundaries
    k_zero_deg<<<(N_NODES + 255) / 256, 256>>>();
    k_hist<<<(N_EDGES / 4 + 255) / 256, 256>>>(dst);
    k_scan1<<<NSCAN_BLOCKS, 1024>>>();
    k_scan2<<<1, 128>>>();
    k_scan3<<<NSCAN_BLOCKS, 1024>>>();
    k_scatter<<<(N_EDGES / 4 + 255) / 256, 256>>>(src, dst);
    k_gbounds<<<(N_NODES + 255) / 256, 256>>>(batch);

    // weight transpose + split (5 conv weights)
    const float* Ws[5] = {c1_w2, c2_w1, c2_w2, c3_w1, c3_w2};
    for (int i = 0; i < 5; ++i)
        k_wprep<<<(HID * HID + 255) / 256, 256>>>(Ws[i], wth + (size_t)i * HID * HID,
                                                  wtl + (size_t)i * HID * HID);

    dim3 gt(4, (N_NODES + 127) / 128);  // 4 n-tiles x 782 m-tiles

    // conv1
    k_agg7<<<(N_NODES + 127) / 128, 128>>>(x);
    k_gemm7<<<(N_NODES + G7_NPB - 1) / G7_NPB, 128>>>(c1_w1, c1_b1, hiA, loA);
    k_tgemm<<<gt, 256, TG_SMEM>>>(hiA, loA, wth + 0 * (size_t)HID * HID, wtl + 0 * (size_t)HID * HID,
                                  c1_b2, hiB, loB, N_NODES);
    // conv2
    k_agg512<<<N_NODES, 128>>>(hiB, loB, hiC, loC);
    k_tgemm<<<gt, 256, TG_SMEM>>>(hiC, loC, wth + 1 * (size_t)HID * HID, wtl + 1 * (size_t)HID * HID,
                                  c2_b1, hiA, loA, N_NODES);
    k_tgemm<<<gt, 256, TG_SMEM>>>(hiA, loA, wth + 2 * (size_t)HID * HID, wtl + 2 * (size_t)HID * HID,
                                  c2_b2, hiB, loB, N_NODES);
    // conv3
    k_agg512<<<N_NODES, 128>>>(hiB, loB, hiC, loC);
    k_tgemm<<<gt, 256, TG_SMEM>>>(hiC, loC, wth + 3 * (size_t)HID * HID, wtl + 3 * (size_t)HID * HID,
                                  c3_b1, hiA, loA, N_NODES);
    k_tgemm<<<gt, 256, TG_SMEM>>>(hiA, loA, wth + 4 * (size_t)HID * HID, wtl + 4 * (size_t)HID * HID,
                                  c3_b2, hiB, loB, N_NODES);

    // mean pool
    k_pool2<<<N_GRAPHS, 128>>>(hiB, loB);

    // head (fp32 FFMA path)
    dim3 ghead(2, (N_GRAPHS + 127) / 128);
    k_sgemm<true><<<ghead, 256>>>(pool, lin_w1, lin_b1, t256, N_GRAPHS, 256, HID);
    k_head2<<<N_GRAPHS, 128>>>(lin_w2, lin_b2, out);
}